// round 16
// baseline (speedup 1.0000x reference)
#include <cuda_runtime.h>
#include <cuda_bf16.h>
#include <cstdint>

#define BMAX    64
#define MA      96
#define NDIM    256
#define EPSF    1e-8f
#define SLAB_F4 2304                 // 96*96/4 float4 per slab
#define NSLABS  (BMAX * MA)          // 6144
#define GRID3   444                  // 3 blocks/SM * 148 SMs = ONE wave
#define NODES_PB 10                  // ceil(4395/444) score nodes per block

// Scatter buffer for padded node scores [B, MAX_A]. Zero-init at module load;
// invalid positions never written (and paths is 0 there anyway).
__device__ float g_sp[BMAX * MA];
// Handshake counters; reset in-kernel by the last block each launch.
__device__ unsigned g_arrive = 0;
__device__ unsigned g_done   = 0;

__device__ __forceinline__ void cp16(float4* dst_smem, const float4* src_gmem) {
    uint32_t d = (uint32_t)__cvta_generic_to_shared(dst_smem);
    asm volatile("cp.async.cg.shared.global [%0], [%1], 16;\n"
                 :: "r"(d), "l"(src_gmem) : "memory");
}
__device__ __forceinline__ void cp_commit() {
    asm volatile("cp.async.commit_group;\n" ::: "memory");
}
__device__ __forceinline__ void cp_wait1() {
    asm volatile("cp.async.wait_group 1;\n" ::: "memory");
}

// ---------------------------------------------------------------------------
// Single persistent kernel, grid = one full residency wave (444 blocks).
//   Phase 0: commit staging for slabs s0 AND s0+nb (72 KB in flight/block).
//   Phase 1: every block computes 10 distinct node scores (x read once
//            across the grid), stores to g_sp, fences. ~0.3us.
//   Barrier: atomic arrive + t0 spin. Co-residency guaranteed (grid == one
//            wave at 74KB smem/block), so the spin cannot deadlock.
//   Phase 2: measured 5.96 TB/s double-buffered slab loop; prologue groups
//            0,1 already committed, loop stages group k+1 for k>0 only.
//   Tail:    last block resets counters -> graph replays are deterministic.
// ---------------------------------------------------------------------------
extern __shared__ float4 s_dyn[];   // [2][SLAB_F4] slabs, then [24] sp

__global__ __launch_bounds__(256) void fused_path_kernel(
        const float*  __restrict__ x,
        const float*  __restrict__ W,
        const float*  __restrict__ bscal,
        const float4* __restrict__ paths4,
        const int*    __restrict__ pad_idx,
        int total,
        float*        __restrict__ out) {
    float4* buf0 = s_dyn;
    float4* buf1 = s_dyn + SLAB_F4;
    float4* sp_s = s_dyn + 2 * SLAB_F4;   // 24 float4 = 96 floats
    const float4* g_sp4 = reinterpret_cast<const float4*>(g_sp);

    int t  = threadIdx.x;
    int nb = gridDim.x;
    int s0 = blockIdx.x;

    // Stage slab -> buffer with XOR swizzle, 9 cp.async per thread.
    auto stage = [&](int slab, float4* dst) {
        if (slab < NSLABS) {
            const float4* src = paths4 + (size_t)slab * SLAB_F4;
            #pragma unroll
            for (int i = 0; i < 9; i++) {
                int f = t + i * 256;
                int r = f / 24;
                int c = f - r * 24;
                cp16(dst + r * 24 + (c ^ (r & 7)), src + f);
            }
        }
        cp_commit();   // unconditional: keeps group numbering exact
    };

    // Phase 0: two slabs in flight before anything else.
    stage(s0,      buf0);                  // group 0
    stage(s0 + nb, buf1);                  // group 1

    // Phase 1: scores, 10 nodes per block spread over the whole grid.
    // 8 lanes per node, single uniform iteration: all shuffles convergent;
    // inactive lanes clamp the load index and suppress only the store.
    {
        int sub = t & 7;
        int n   = blockIdx.x * NODES_PB + (t >> 3);
        bool active = ((t >> 3) < NODES_PB) && (n < total);
        int nc  = active ? n : (total - 1);

        const float4* wr = reinterpret_cast<const float4*>(W);
        const float4* xr = reinterpret_cast<const float4*>(x + (size_t)nc * NDIM);
        float s = 0.0f;
        #pragma unroll
        for (int i = 0; i < 8; i++) {
            float4 a  = xr[sub + 8 * i];
            float4 ww = wr[sub + 8 * i];
            s += a.x * ww.x + a.y * ww.y + a.z * ww.z + a.w * ww.w;
        }
        s += __shfl_xor_sync(0xFFFFFFFFu, s, 1);
        s += __shfl_xor_sync(0xFFFFFFFFu, s, 2);
        s += __shfl_xor_sync(0xFFFFFFFFu, s, 4);
        if (active && sub == 0)
            g_sp[pad_idx[n]] = s + bscal[0];
    }
    __threadfence();                       // publish g_sp stores (gpu scope)

    // Grid handshake: arrive, then t0 spins until all 444 blocks arrived.
    if (t == 0) {
        atomicAdd(&g_arrive, 1u);
        while (atomicAdd(&g_arrive, 0u) < (unsigned)GRID3)
            __nanosleep(64);
    }
    __syncthreads();
    __threadfence();                       // acquire: g_sp reads see all stores

    // Phase 2: double-buffered slab loop (measured 5.96 TB/s structure).
    int k = 0;
    for (int s = s0; s < NSLABS; s += nb, k++) {
        if (t < 24) sp_s[t] = g_sp4[(s / MA) * 24 + t];

        float4* cur = (k & 1) ? buf1 : buf0;
        float4* nxt = (k & 1) ? buf0 : buf1;
        if (k > 0) stage(s + nb, nxt);     // group k+1 (0,1 pre-committed)

        cp_wait1();              // group k done -> slab s resident
        __syncthreads();

        if (t < 192) {
            int r  = t >> 1;
            int h  = t & 1;
            int sw = r & 7;
            const float4* row = cur + r * 24;
            float num = 0.0f, den = 0.0f;
            #pragma unroll
            for (int j = 0; j < 12; j++) {
                int c = h * 12 + j;
                float4 p  = row[c ^ sw];
                float4 sv = sp_s[c];
                num += p.x * sv.x + p.y * sv.y + p.z * sv.z + p.w * sv.w;
                den += (p.x + p.y) + (p.z + p.w);
            }
            num += __shfl_xor_sync(0xFFFFFFFFu, num, 1);
            den += __shfl_xor_sync(0xFFFFFFFFu, den, 1);
            if (h == 0)
                out[(size_t)s * MA + r] = num / (den + EPSF);
        }
        __syncthreads();         // cur + sp_s free for reuse
    }

    // Tail: last block to finish resets both counters for the next replay.
    if (t == 0) {
        unsigned d = atomicAdd(&g_done, 1u);
        if (d == (unsigned)(GRID3 - 1)) {
            g_arrive = 0;
            g_done   = 0;
            __threadfence();
        }
    }
}

// ---------------------------------------------------------------------------
// Launch. Inputs (metadata order): x, W, b, paths, pad_idx.
// ---------------------------------------------------------------------------
extern "C" void kernel_launch(void* const* d_in, const int* in_sizes, int n_in,
                              void* d_out, int out_size) {
    const float*  x       = (const float*)d_in[0];
    const float*  W       = (const float*)d_in[1];
    const float*  bscal   = (const float*)d_in[2];
    const float4* paths4  = (const float4*)d_in[3];
    const int*    pad_idx = (const int*)d_in[4];
    float*        out     = (float*)d_out;

    int total = in_sizes[4];

    size_t smem = (2 * SLAB_F4 + 24) * sizeof(float4);   // 74112 B
    cudaFuncSetAttribute(fused_path_kernel,
                         cudaFuncAttributeMaxDynamicSharedMemorySize,
                         (int)smem);
    fused_path_kernel<<<GRID3, 256, smem>>>(x, W, bscal, paths4, pad_idx,
                                            total, out);
}

// round 17
// speedup vs baseline: 1.0920x; 1.0920x over previous
#include <cuda_runtime.h>
#include <cuda_bf16.h>
#include <cstdint>

#define BMAX    64
#define MA      96
#define NDIM    256
#define EPSF    1e-8f
#define SLAB_F4 2304                 // 96*96/4 float4 per slab
#define NSLABS  (BMAX * MA)          // 6144
#define GRID3   444                  // 3 blocks per SM * 148 SMs

// Scatter buffer for padded node scores [B, MAX_A]. Zero-init at module load;
// invalid positions never written (and paths is 0 there anyway).
__device__ float g_sp[BMAX * MA];

__device__ __forceinline__ void cp16(float4* dst_smem, const float4* src_gmem) {
    uint32_t d = (uint32_t)__cvta_generic_to_shared(dst_smem);
    asm volatile("cp.async.cg.shared.global [%0], [%1], 16;\n"
                 :: "r"(d), "l"(src_gmem) : "memory");
}
__device__ __forceinline__ void cp_commit() {
    asm volatile("cp.async.commit_group;\n" ::: "memory");
}
__device__ __forceinline__ void cp_wait1() {
    asm volatile("cp.async.wait_group 1;\n" ::: "memory");
}
// PDL primitives (sm_90+)
__device__ __forceinline__ void pdl_trigger() {
    asm volatile("griddepcontrol.launch_dependents;" ::: "memory");
}
__device__ __forceinline__ void pdl_wait() {
    asm volatile("griddepcontrol.wait;" ::: "memory");
}

// ---------------------------------------------------------------------------
// Kernel 1: scores = x @ W[0] + b[0], scattered into g_sp via pad_idx.
// 8 lanes per node, single uniform iteration (convergent shuffles).
// Triggers dependent (path) launch after publishing its stores.
// ---------------------------------------------------------------------------
__global__ __launch_bounds__(256) void score_scatter_kernel(
        const float* __restrict__ x,
        const float* __restrict__ W,
        const float* __restrict__ bscal,
        const int*   __restrict__ pad_idx,
        int total) {
    int t    = threadIdx.x;
    int sub  = t & 7;
    int n    = blockIdx.x * 32 + (t >> 3);
    bool active = n < total;
    int nc   = active ? n : (total - 1);

    const float4* wr = reinterpret_cast<const float4*>(W);
    const float4* xr = reinterpret_cast<const float4*>(x + (size_t)nc * NDIM);

    float s = 0.0f;
    #pragma unroll
    for (int i = 0; i < 8; i++) {
        float4 a  = xr[sub + 8 * i];
        float4 ww = wr[sub + 8 * i];
        s += a.x * ww.x + a.y * ww.y + a.z * ww.z + a.w * ww.w;
    }
    s += __shfl_xor_sync(0xFFFFFFFFu, s, 1);
    s += __shfl_xor_sync(0xFFFFFFFFu, s, 2);
    s += __shfl_xor_sync(0xFFFFFFFFu, s, 4);

    if (active && sub == 0)
        g_sp[pad_idx[n]] = s + bscal[0];

    __threadfence();     // publish g_sp before signalling dependents
    pdl_trigger();
}

// ---------------------------------------------------------------------------
// Kernel 2: persistent double-buffered cp.async pipeline, 3 blocks/SM.
// Launched with programmatic stream serialization: blocks start while the
// score kernel is still running, commit BOTH slab buffers (72 KB in flight,
// no g_sp dependency), then griddepcontrol.wait before reading g_sp.
// Main loop is the measured 5.96 TB/s structure (groups 0,1 pre-committed;
// iteration k stages group k+1 for k>0; wait_group 1 => slab k resident).
// ---------------------------------------------------------------------------
extern __shared__ float4 s_dyn[];   // [2][SLAB_F4] slabs, then [24] sp

__global__ __launch_bounds__(256) void path_avg_kernel(
        const float4* __restrict__ paths4,
        float*        __restrict__ out) {
    float4* buf0 = s_dyn;
    float4* buf1 = s_dyn + SLAB_F4;
    float4* sp_s = s_dyn + 2 * SLAB_F4;   // 24 float4 = 96 floats
    const float4* g_sp4 = reinterpret_cast<const float4*>(g_sp);

    int t  = threadIdx.x;
    int nb = gridDim.x;
    int s0 = blockIdx.x;

    // Stage slab -> buffer with XOR swizzle, 9 cp.async per thread.
    auto stage = [&](int slab, float4* dst) {
        if (slab < NSLABS) {
            const float4* src = paths4 + (size_t)slab * SLAB_F4;
            #pragma unroll
            for (int i = 0; i < 9; i++) {
                int f = t + i * 256;
                int r = f / 24;
                int c = f - r * 24;
                cp16(dst + r * 24 + (c ^ (r & 7)), src + f);
            }
        }
        cp_commit();   // unconditional: keeps group numbering exact
    };

    // Prologue (independent of g_sp): both buffers committed.
    stage(s0,      buf0);   // group 0
    stage(s0 + nb, buf1);   // group 1

    // Wait for the score kernel's completion signal before touching g_sp.
    pdl_wait();

    int k = 0;
    for (int s = s0; s < NSLABS; s += nb, k++) {
        if (t < 24) sp_s[t] = g_sp4[(s / MA) * 24 + t];

        float4* cur = (k & 1) ? buf1 : buf0;
        float4* nxt = (k & 1) ? buf0 : buf1;
        if (k > 0) stage(s + nb, nxt);     // group k+1 (0,1 pre-committed)

        cp_wait1();              // group k done -> slab s resident
        __syncthreads();

        if (t < 192) {
            int r  = t >> 1;
            int h  = t & 1;
            int sw = r & 7;
            const float4* row = cur + r * 24;
            float num = 0.0f, den = 0.0f;
            #pragma unroll
            for (int j = 0; j < 12; j++) {
                int c = h * 12 + j;
                float4 p  = row[c ^ sw];
                float4 sv = sp_s[c];
                num += p.x * sv.x + p.y * sv.y + p.z * sv.z + p.w * sv.w;
                den += (p.x + p.y) + (p.z + p.w);
            }
            num += __shfl_xor_sync(0xFFFFFFFFu, num, 1);
            den += __shfl_xor_sync(0xFFFFFFFFu, den, 1);
            if (h == 0)
                out[(size_t)s * MA + r] = num / (den + EPSF);
        }
        __syncthreads();         // cur + sp_s free for reuse
    }
}

// ---------------------------------------------------------------------------
// Launch. Inputs (metadata order): x, W, b, paths, pad_idx.
// Path kernel launched with programmatic stream serialization (PDL).
// ---------------------------------------------------------------------------
extern "C" void kernel_launch(void* const* d_in, const int* in_sizes, int n_in,
                              void* d_out, int out_size) {
    const float*  x       = (const float*)d_in[0];
    const float*  W       = (const float*)d_in[1];
    const float*  bscal   = (const float*)d_in[2];
    const float4* paths4  = (const float4*)d_in[3];
    const int*    pad_idx = (const int*)d_in[4];
    float*        out     = (float*)d_out;

    int total = in_sizes[4];

    // 1: scores + scatter (8 lanes per node, 32 nodes per block)
    int blocks1 = (total + 31) / 32;
    score_scatter_kernel<<<blocks1, 256>>>(x, W, bscal, pad_idx, total);

    // 2: path pass, PDL-overlapped with kernel 1.
    size_t smem = (2 * SLAB_F4 + 24) * sizeof(float4);   // 74112 B
    cudaFuncSetAttribute(path_avg_kernel,
                         cudaFuncAttributeMaxDynamicSharedMemorySize,
                         (int)smem);

    cudaLaunchConfig_t cfg = {};
    cfg.gridDim          = dim3(GRID3, 1, 1);
    cfg.blockDim         = dim3(256, 1, 1);
    cfg.dynamicSmemBytes = smem;
    cfg.stream           = 0;
    cudaLaunchAttribute attrs[1];
    attrs[0].id = cudaLaunchAttributeProgrammaticStreamSerialization;
    attrs[0].val.programmaticStreamSerializationAllowed = 1;
    cfg.attrs    = attrs;
    cfg.numAttrs = 1;
    cudaLaunchKernelEx(&cfg, path_avg_kernel, paths4, out);
}